// round 11
// baseline (speedup 1.0000x reference)
#include <cuda_runtime.h>
#include <cuda_fp16.h>
#include <math.h>

// ---------------- problem constants ----------------
#define T_      1024
#define H_      2048
#define I_      1024
#define E_      16            // routed experts; index E_ = shared expert
#define TWOI_   2048
#define G_      4
#define EPG_    4
#define TOPK_   4
#define NPAIR_  (T_*TOPK_)    // 4096 routed slots; shared slots are NPAIR_+t
#define NROWS_  (NPAIR_+T_)   // 5120 act rows
#define RSCALE_ 2.5f

// ---------------- device scratch (no allocations allowed) ----------------
__device__ __half d_x16 [(size_t)T_*H_];       // x converted to fp16
__device__ __half d_act [(size_t)NROWS_*I_];   // silu(g)*u*w, fp16, by slot
__device__ int    d_cnt [E_+1];
__device__ int    d_tok [(E_+1)*T_];           // gather: token per expert entry
__device__ int    d_dst [(E_+1)*T_];           // slot per expert entry
__device__ float  d_wslot[NPAIR_];             // routing weight per routed slot

// ---------------- fp16 pack helper ----------------
__device__ __forceinline__ unsigned pack_h2(float lo, float hi) {
    unsigned r;
    asm("cvt.rn.f16x2.f32 %0, %1, %2;" : "=r"(r) : "f"(hi), "f"(lo));
    return r;
}

// ---------------- init: reset counters, build shared-expert lists ----------------
__global__ void init_kernel() {
    int idx = blockIdx.x * blockDim.x + threadIdx.x;
    if (idx < T_) {
        d_tok[E_*T_ + idx] = idx;
        d_dst[E_*T_ + idx] = NPAIR_ + idx;
    }
    if (idx < E_) d_cnt[idx] = 0;
    if (idx == E_) d_cnt[E_] = T_;
}

// ---------------- x -> fp16 (8 elems/thread) ----------------
__global__ void cvt_x_kernel(const float* __restrict__ x) {
    int i = blockIdx.x * blockDim.x + threadIdx.x;   // over T_*H_/8
    const float4* s = (const float4*)x + (size_t)i*2;
    float4 v0 = s[0], v1 = s[1];
    uint4 o;
    o.x = pack_h2(v0.x, v0.y); o.y = pack_h2(v0.z, v0.w);
    o.z = pack_h2(v1.x, v1.y); o.w = pack_h2(v1.z, v1.w);
    ((uint4*)d_x16)[i] = o;
}

// ---------------- router (fp32 exact, replicates reference grouped top-k) ----------------
__global__ void router_kernel(const float* __restrict__ x,
                              const float* __restrict__ gate_w,
                              const float* __restrict__ e_bias) {
    int t = blockIdx.x;
    int warp = threadIdx.x >> 5;
    int lane = threadIdx.x & 31;
    const float* xr = x + (size_t)t * H_;
    const float* wr = gate_w + (size_t)warp * H_;
    float s = 0.f;
    for (int h = lane; h < H_; h += 32) s += xr[h] * wr[h];
    #pragma unroll
    for (int o = 16; o; o >>= 1) s += __shfl_xor_sync(0xFFFFFFFFu, s, o);
    __shared__ float logit[E_];
    if (lane == 0) logit[warp] = s;
    __syncthreads();
    if (threadIdx.x == 0) {
        float sc[E_], sb[E_];
        #pragma unroll
        for (int e = 0; e < E_; e++) {
            sc[e] = 1.f / (1.f + expf(-logit[e]));
            sb[e] = sc[e] + e_bias[e];
        }
        float gs[G_];
        #pragma unroll
        for (int g = 0; g < G_; g++) {
            float m1 = -INFINITY, m2 = -INFINITY;
            #pragma unroll
            for (int i = 0; i < EPG_; i++) {
                float v = sb[g*EPG_ + i];
                if (v > m1) { m2 = m1; m1 = v; }
                else if (v > m2) { m2 = v; }
            }
            gs[g] = m1 + m2;
        }
        int g1 = 0;
        for (int g = 1; g < G_; g++) if (gs[g] > gs[g1]) g1 = g;
        int g2 = -1;
        for (int g = 0; g < G_; g++) {
            if (g == g1) continue;
            if (g2 < 0 || gs[g] > gs[g2]) g2 = g;
        }
        float tmp[E_];
        #pragma unroll
        for (int e = 0; e < E_; e++) {
            int g = e / EPG_;
            tmp[e] = (g == g1 || g == g2) ? sb[e] : 0.f;
        }
        bool taken[E_];
        #pragma unroll
        for (int e = 0; e < E_; e++) taken[e] = false;
        int ids[TOPK_]; float wv[TOPK_]; float wsum = 0.f;
        #pragma unroll
        for (int k = 0; k < TOPK_; k++) {
            int bi = -1; float bv = -INFINITY;
            for (int e = 0; e < E_; e++) {
                if (!taken[e] && tmp[e] > bv) { bv = tmp[e]; bi = e; }
            }
            taken[bi] = true;
            ids[k] = bi;
            wv[k] = sc[bi];
            wsum += wv[k];
        }
        float inv = 1.f / wsum;
        #pragma unroll
        for (int k = 0; k < TOPK_; k++) {
            int e = ids[k];
            int pos = atomicAdd(&d_cnt[e], 1);
            d_tok[e*T_ + pos] = t;
            d_dst[e*T_ + pos] = t*TOPK_ + k;
            d_wslot[t*TOPK_ + k] = wv[k] * inv;
        }
    }
}

// ---------------- mma / ldmatrix / cp.async helpers ----------------
__device__ __forceinline__ void mma_f16(float c[4], const unsigned a[4], const unsigned b[2]) {
    asm volatile(
        "mma.sync.aligned.m16n8k16.row.col.f32.f16.f16.f32 "
        "{%0,%1,%2,%3}, {%4,%5,%6,%7}, {%8,%9}, {%0,%1,%2,%3};"
        : "+f"(c[0]), "+f"(c[1]), "+f"(c[2]), "+f"(c[3])
        : "r"(a[0]), "r"(a[1]), "r"(a[2]), "r"(a[3]), "r"(b[0]), "r"(b[1]));
}
__device__ __forceinline__ void ldsm4(unsigned &r0, unsigned &r1, unsigned &r2, unsigned &r3,
                                      unsigned addr) {
    asm volatile("ldmatrix.sync.aligned.m8n8.x4.shared.b16 {%0,%1,%2,%3}, [%4];"
                 : "=r"(r0), "=r"(r1), "=r"(r2), "=r"(r3) : "r"(addr));
}
__device__ __forceinline__ void red_add_v2(float* ptr, float v0, float v1) {
    asm volatile("red.global.add.v2.f32 [%0], {%1, %2};"
                 :: "l"(ptr), "f"(v0), "f"(v1) : "memory");
}
__device__ __forceinline__ void cpa16(unsigned dst, const void* src, int sz) {
    asm volatile("cp.async.cg.shared.global [%0], [%1], 16, %2;"
                 :: "r"(dst), "l"(src), "r"(sz) : "memory");
}
__device__ __forceinline__ void cpa_commit() {
    asm volatile("cp.async.commit_group;" ::: "memory");
}
__device__ __forceinline__ void cpa_wait0() {
    asm volatile("cp.async.wait_group 0;" ::: "memory");
}
__device__ __forceinline__ float silu_mul(float g, float u) {
    return (g / (1.f + expf(-g))) * u;
}

// ---------------- shared GEMM geometry ----------------
// CTA tile 128(M) x 256(N), BK=16, 256 threads = 8 warps (2 wm x 4 wn),
// warp tile 64x64. A (fp16) staged by cp.async; B (fp32) LDG+cvt+STS.
// smem row stride 12 words (8 data + 4 pad): ldsm chunk pattern 3r mod 8
// and STS chunks are conflict-free.
#define RS   12
#define AROWS 128
#define BROWS 256

// fragment loads + 32 MMAs for one k16 tile (shared by both GEMMs)
#define GEMM_TILE_COMPUTE()                                                    \
    do {                                                                       \
        unsigned a[4][4], b[8][2];                                             \
        _Pragma("unroll")                                                      \
        for (int mt = 0; mt < 4; mt++)                                         \
            ldsm4(a[mt][0], a[mt][1], a[mt][2], a[mt][3],                      \
                  ab + (unsigned)(((a_r + mt*16)*RS + a_w) * 4));              \
        _Pragma("unroll")                                                      \
        for (int p = 0; p < 4; p++)                                            \
            ldsm4(b[2*p][0], b[2*p][1], b[2*p+1][0], b[2*p+1][1],              \
                  bb + (unsigned)(((b_r + p*16)*RS + b_w) * 4));               \
        _Pragma("unroll")                                                      \
        for (int mt = 0; mt < 4; mt++)                                         \
            _Pragma("unroll")                                                  \
            for (int nt = 0; nt < 8; nt++)                                     \
                mma_f16(acc[mt][nt], a[mt], b[nt]);                            \
    } while (0)

// ============ fused gate_up GEMM + silu*mul*w -> fp16 act ============
// grid (I/128, T/128, E+1). Expert E = shared. N=256 B rows = 128 act cols,
// interleaved gate/up so each thread's mma col pair = (gate j, up j).
__global__ void __launch_bounds__(256, 1)
gu_silu_gemm(const __half* __restrict__ X16,
             const float* __restrict__ Wgu,    // [E,2I,H]
             const float* __restrict__ Sgu,    // [2I,H]
             __half* __restrict__ Act,
             const int* __restrict__ counts,
             const int* __restrict__ tok,
             const int* __restrict__ dst,
             const float* __restrict__ wslot)
{
    const int e = blockIdx.z;
    const int M = counts[e];
    const int m0 = blockIdx.y * 128;
    if (m0 >= M) return;
    const int n0a = blockIdx.x * 128;   // act column block (128 cols = 256 B rows)
    const float* W = (e == E_) ? Sgu : (Wgu + (size_t)e * TWOI_ * H_);
    const int K = H_;

    __shared__ unsigned As[2][AROWS*RS];
    __shared__ unsigned Bs[2][BROWS*RS];

    const int tid  = threadIdx.x;
    const int lane = tid & 31;
    const int warp = tid >> 5;
    const int wm   = warp >> 2;        // 0..1, 64 M-rows
    const int wn   = warp & 3;         // 0..3, 64 cols
    const int g    = lane >> 2;
    const int tg   = lane & 3;

    // A staging: thread -> row tid>>1, k-half (tid&1)*8 halves, 1 cp.async
    const int alr = tid >> 1;
    const int akh = (tid & 1) * 8;
    const bool a_ok = (m0 + alr) < M;
    const int asz = a_ok ? 16 : 0;
    long arow = 0;
    if (a_ok) arow = (long)tok[e*T_ + m0 + alr];
    const __half* Ag = X16 + arow * H_ + akh;

    // B staging: thread -> B row tid (interleaved gate/up weight row), 16 fp32
    const long brow = (long)((tid & 1) * I_ + n0a + (tid >> 1));
    const float* Bg = W + brow * K;

    const int ntiles = K >> 4;   // BK = 16

    const unsigned aBuf[2] = { (unsigned)__cvta_generic_to_shared(As[0]),
                               (unsigned)__cvta_generic_to_shared(As[1]) };
    const unsigned bBuf[2] = { (unsigned)__cvta_generic_to_shared(Bs[0]),
                               (unsigned)__cvta_generic_to_shared(Bs[1]) };
    const unsigned aOff = (unsigned)((alr*RS + (tid & 1)*4) * 4);

    // prologue: A_0, B_0
    cpa16(aBuf[0] + aOff, Ag, asz);
    cpa_commit();
    float4 pb[4];
    #pragma unroll
    for (int c = 0; c < 4; c++) pb[c] = *(const float4*)(Bg + c*4);

    float acc[4][8][4];
    #pragma unroll
    for (int mt = 0; mt < 4; mt++)
        #pragma unroll
        for (int nt = 0; nt < 8; nt++)
            #pragma unroll
            for (int i = 0; i < 4; i++) acc[mt][nt][i] = 0.f;

    const int ml = lane >> 3, rl = lane & 7;
    const int a_r = wm*64 + (ml & 1)*8 + rl;
    const int a_w = (ml >> 1) * 4;
    const int b_r = wn*64 + (ml >> 1)*8 + rl;
    const int b_w = (ml & 1) * 4;

    for (int kt = 0; kt < ntiles; kt++) {
        const int buf = kt & 1;
        // stage B_kt (cvt fp32->fp16x2), 2x STS.128 at row tid
        unsigned* bs = &Bs[buf][tid*RS];
        {
            uint4 w0, w1;
            w0.x = pack_h2(pb[0].x, pb[0].y); w0.y = pack_h2(pb[0].z, pb[0].w);
            w0.z = pack_h2(pb[1].x, pb[1].y); w0.w = pack_h2(pb[1].z, pb[1].w);
            w1.x = pack_h2(pb[2].x, pb[2].y); w1.y = pack_h2(pb[2].z, pb[2].w);
            w1.z = pack_h2(pb[3].x, pb[3].y); w1.w = pack_h2(pb[3].z, pb[3].w);
            *(uint4*)(bs)     = w0;
            *(uint4*)(bs + 4) = w1;
        }
        // prefetch B_{kt+1}
        if (kt + 1 < ntiles) {
            const float* bg = Bg + (kt+1)*16;
            #pragma unroll
            for (int c = 0; c < 4; c++) pb[c] = *(const float4*)(bg + c*4);
        }
        cpa_wait0();
        __syncthreads();
        // refill the other A buffer (all warps done reading it)
        if (kt + 1 < ntiles)
            cpa16(aBuf[buf ^ 1] + aOff, Ag + (kt+1)*16, asz);
        cpa_commit();

        const unsigned ab = aBuf[buf];
        const unsigned bb = bBuf[buf];
        GEMM_TILE_COMPUTE();
    }

    // epilogue: col pair = (gate j, up j); act col = wn*32 + nt*4 + tg
    #pragma unroll
    for (int mt = 0; mt < 4; mt++) {
        #pragma unroll
        for (int half = 0; half < 2; half++) {
            int lm = m0 + wm*64 + mt*16 + g + half*8;
            if (lm < M) {
                long crow = (long)dst[e*T_ + lm];
                float w = (crow < NPAIR_) ? wslot[crow] : 1.f;
                __half* Cp = Act + crow * I_ + n0a + wn*32 + tg;
                #pragma unroll
                for (int nt = 0; nt < 8; nt++) {
                    float gv = acc[mt][nt][half*2 + 0];
                    float uv = acc[mt][nt][half*2 + 1];
                    Cp[nt*4] = __float2half_rn(w * silu_mul(gv, uv));
                }
            }
        }
    }
}

// ============ down GEMM ============
// grid (H/256, T/128, experts). A = fp16 act via cp.async; B fp32 weights.
// SHARED=true : plain store into out (initializes it).
// SHARED=false: gather by slot, red.v2 accumulate 2.5*y.
template<bool SHARED>
__global__ void __launch_bounds__(256, 1)
down_gemm(const __half* __restrict__ Act,
          const float* __restrict__ Wbase,   // SHARED: [H,I], else [E,H,I]
          float* __restrict__ Out,
          const int* __restrict__ counts,
          const int* __restrict__ dst)
{
    const int e = SHARED ? 0 : blockIdx.z;
    const int M = SHARED ? T_ : counts[e];
    const int m0 = blockIdx.y * 128;
    if (m0 >= M) return;
    const int n0 = blockIdx.x * 256;
    const float* W = SHARED ? Wbase : (Wbase + (size_t)e * H_ * I_);
    const int K = I_;

    __shared__ unsigned As[2][AROWS*RS];
    __shared__ unsigned Bs[2][BROWS*RS];

    const int tid  = threadIdx.x;
    const int lane = tid & 31;
    const int warp = tid >> 5;
    const int wm   = warp >> 2;
    const int wn   = warp & 3;
    const int g    = lane >> 2;
    const int tg   = lane & 3;

    const int alr = tid >> 1;
    const int akh = (tid & 1) * 8;
    const bool a_ok = (m0 + alr) < M;
    const int asz = a_ok ? 16 : 0;
    long arow = 0;
    if (a_ok) arow = SHARED ? (long)(NPAIR_ + m0 + alr) : (long)dst[e*T_ + m0 + alr];
    const __half* Ag = Act + arow * I_ + akh;

    const float* Bg = W + (long)(n0 + tid) * K;

    const int ntiles = K >> 4;

    const unsigned aBuf[2] = { (unsigned)__cvta_generic_to_shared(As[0]),
                               (unsigned)__cvta_generic_to_shared(As[1]) };
    const unsigned bBuf[2] = { (unsigned)__cvta_generic_to_shared(Bs[0]),
                               (unsigned)__cvta_generic_to_shared(Bs[1]) };
    const unsigned aOff = (unsigned)((alr*RS + (tid & 1)*4) * 4);

    cpa16(aBuf[0] + aOff, Ag, asz);
    cpa_commit();
    float4 pb[4];
    #pragma unroll
    for (int c = 0; c < 4; c++) pb[c] = *(const float4*)(Bg + c*4);

    float acc[4][8][4];
    #pragma unroll
    for (int mt = 0; mt < 4; mt++)
        #pragma unroll
        for (int nt = 0; nt < 8; nt++)
            #pragma unroll
            for (int i = 0; i < 4; i++) acc[mt][nt][i] = 0.f;

    const int ml = lane >> 3, rl = lane & 7;
    const int a_r = wm*64 + (ml & 1)*8 + rl;
    const int a_w = (ml >> 1) * 4;
    const int b_r = wn*64 + (ml >> 1)*8 + rl;
    const int b_w = (ml & 1) * 4;

    for (int kt = 0; kt < ntiles; kt++) {
        const int buf = kt & 1;
        unsigned* bs = &Bs[buf][tid*RS];
        {
            uint4 w0, w1;
            w0.x = pack_h2(pb[0].x, pb[0].y); w0.y = pack_h2(pb[0].z, pb[0].w);
            w0.z = pack_h2(pb[1].x, pb[1].y); w0.w = pack_h2(pb[1].z, pb[1].w);
            w1.x = pack_h2(pb[2].x, pb[2].y); w1.y = pack_h2(pb[2].z, pb[2].w);
            w1.z = pack_h2(pb[3].x, pb[3].y); w1.w = pack_h2(pb[3].z, pb[3].w);
            *(uint4*)(bs)     = w0;
            *(uint4*)(bs + 4) = w1;
        }
        if (kt + 1 < ntiles) {
            const float* bg = Bg + (kt+1)*16;
            #pragma unroll
            for (int c = 0; c < 4; c++) pb[c] = *(const float4*)(bg + c*4);
        }
        cpa_wait0();
        __syncthreads();
        if (kt + 1 < ntiles)
            cpa16(aBuf[buf ^ 1] + aOff, Ag + (kt+1)*16, asz);
        cpa_commit();

        const unsigned ab = aBuf[buf];
        const unsigned bb = bBuf[buf];
        GEMM_TILE_COMPUTE();
    }

    #pragma unroll
    for (int mt = 0; mt < 4; mt++) {
        #pragma unroll
        for (int half = 0; half < 2; half++) {
            int lm = m0 + wm*64 + mt*16 + g + half*8;
            if (lm < M) {
                if (SHARED) {
                    float* Cp = Out + (long)lm * H_ + n0 + wn*64 + 2*tg;
                    #pragma unroll
                    for (int nt = 0; nt < 8; nt++) {
                        float2 v;
                        v.x = acc[mt][nt][half*2 + 0];
                        v.y = acc[mt][nt][half*2 + 1];
                        *(float2*)(Cp + nt*8) = v;
                    }
                } else {
                    int slot = dst[e*T_ + lm];
                    float* Cp = Out + (long)(slot >> 2) * H_ + n0 + wn*64 + 2*tg;
                    #pragma unroll
                    for (int nt = 0; nt < 8; nt++) {
                        red_add_v2(Cp + nt*8,
                                   RSCALE_ * acc[mt][nt][half*2 + 0],
                                   RSCALE_ * acc[mt][nt][half*2 + 1]);
                    }
                }
            }
        }
    }
}

// ---------------- launcher ----------------
extern "C" void kernel_launch(void* const* d_in, const int* in_sizes, int n_in,
                              void* d_out, int out_size) {
    const float* x        = (const float*)d_in[0];
    const float* gate_w   = (const float*)d_in[1];
    const float* e_bias   = (const float*)d_in[2];
    const float* w_gu     = (const float*)d_in[3];
    const float* w_dn     = (const float*)d_in[4];
    const float* s_wgu    = (const float*)d_in[5];
    const float* s_wdn    = (const float*)d_in[6];
    float* out = (float*)d_out;

    __half *p_x16, *p_act; float* p_wslot;
    int *p_cnt, *p_tok, *p_dst;
    cudaGetSymbolAddress((void**)&p_x16,   d_x16);
    cudaGetSymbolAddress((void**)&p_act,   d_act);
    cudaGetSymbolAddress((void**)&p_wslot, d_wslot);
    cudaGetSymbolAddress((void**)&p_cnt,   d_cnt);
    cudaGetSymbolAddress((void**)&p_tok,   d_tok);
    cudaGetSymbolAddress((void**)&p_dst,   d_dst);

    // 1. reset counters + shared-expert gather lists
    init_kernel<<<(T_ + 255)/256, 256>>>();

    // 1b. x -> fp16
    cvt_x_kernel<<<(T_*H_/8 + 255)/256, 256>>>(x);

    // 2. router (fp32 exact)
    router_kernel<<<T_, 512>>>(x, gate_w, e_bias);

    // 3. all gate_up + silu (+w): routed experts AND shared (z = E_)
    gu_silu_gemm<<<dim3(I_/128, T_/128, E_+1), 256>>>(
        p_x16, w_gu, s_wgu, p_act, p_cnt, p_tok, p_dst, p_wslot);

    // 4. shared down: plain store initializes out
    down_gemm<true><<<dim3(H_/256, T_/128, 1), 256>>>(
        p_act, s_wdn, out, p_cnt, p_dst);

    // 5. routed down: red.v2 accumulate 2.5*y into out
    down_gemm<false><<<dim3(H_/256, T_/128, E_), 256>>>(
        p_act, w_dn, out, p_cnt, p_dst);
}

// round 12
// speedup vs baseline: 1.4310x; 1.4310x over previous
#include <cuda_runtime.h>
#include <cuda_fp16.h>
#include <math.h>

// ---------------- problem constants ----------------
#define T_      1024
#define H_      2048
#define I_      1024
#define E_      16            // routed experts; index E_ = shared expert
#define TWOI_   2048
#define G_      4
#define EPG_    4
#define TOPK_   4
#define NPAIR_  (T_*TOPK_)    // 4096 routed slots; shared slots are NPAIR_+t
#define NROWS_  (NPAIR_+T_)   // 5120 act rows
#define RSCALE_ 2.5f

// ---------------- device scratch (no allocations allowed) ----------------
__device__ __half d_x16 [(size_t)T_*H_];       // x converted to fp16
__device__ __half d_act [(size_t)NROWS_*I_];   // silu(g)*u*w, fp16, by slot
__device__ int    d_cnt [E_+1];
__device__ int    d_tok [(E_+1)*T_];           // gather: token per expert entry
__device__ int    d_dst [(E_+1)*T_];           // slot per expert entry
__device__ float  d_wslot[NPAIR_];             // routing weight per routed slot

// ---------------- fp16 pack helper ----------------
__device__ __forceinline__ unsigned pack_h2(float lo, float hi) {
    unsigned r;
    asm("cvt.rn.f16x2.f32 %0, %1, %2;" : "=r"(r) : "f"(hi), "f"(lo));
    return r;
}

// ---------------- init: reset counters, build shared-expert lists ----------------
__global__ void init_kernel() {
    int idx = blockIdx.x * blockDim.x + threadIdx.x;
    if (idx < T_) {
        d_tok[E_*T_ + idx] = idx;
        d_dst[E_*T_ + idx] = NPAIR_ + idx;
    }
    if (idx < E_) d_cnt[idx] = 0;
    if (idx == E_) d_cnt[E_] = T_;
}

// ---------------- x -> fp16 (8 elems/thread) ----------------
__global__ void cvt_x_kernel(const float* __restrict__ x) {
    int i = blockIdx.x * blockDim.x + threadIdx.x;   // over T_*H_/8
    const float4* s = (const float4*)x + (size_t)i*2;
    float4 v0 = s[0], v1 = s[1];
    uint4 o;
    o.x = pack_h2(v0.x, v0.y); o.y = pack_h2(v0.z, v0.w);
    o.z = pack_h2(v1.x, v1.y); o.w = pack_h2(v1.z, v1.w);
    ((uint4*)d_x16)[i] = o;
}

// ---------------- router (fp32 exact, replicates reference grouped top-k) ----------------
__global__ void router_kernel(const float* __restrict__ x,
                              const float* __restrict__ gate_w,
                              const float* __restrict__ e_bias) {
    int t = blockIdx.x;
    int warp = threadIdx.x >> 5;
    int lane = threadIdx.x & 31;
    const float* xr = x + (size_t)t * H_;
    const float* wr = gate_w + (size_t)warp * H_;
    float s = 0.f;
    for (int h = lane; h < H_; h += 32) s += xr[h] * wr[h];
    #pragma unroll
    for (int o = 16; o; o >>= 1) s += __shfl_xor_sync(0xFFFFFFFFu, s, o);
    __shared__ float logit[E_];
    if (lane == 0) logit[warp] = s;
    __syncthreads();
    if (threadIdx.x == 0) {
        float sc[E_], sb[E_];
        #pragma unroll
        for (int e = 0; e < E_; e++) {
            sc[e] = 1.f / (1.f + expf(-logit[e]));
            sb[e] = sc[e] + e_bias[e];
        }
        float gs[G_];
        #pragma unroll
        for (int g = 0; g < G_; g++) {
            float m1 = -INFINITY, m2 = -INFINITY;
            #pragma unroll
            for (int i = 0; i < EPG_; i++) {
                float v = sb[g*EPG_ + i];
                if (v > m1) { m2 = m1; m1 = v; }
                else if (v > m2) { m2 = v; }
            }
            gs[g] = m1 + m2;
        }
        int g1 = 0;
        for (int g = 1; g < G_; g++) if (gs[g] > gs[g1]) g1 = g;
        int g2 = -1;
        for (int g = 0; g < G_; g++) {
            if (g == g1) continue;
            if (g2 < 0 || gs[g] > gs[g2]) g2 = g;
        }
        float tmp[E_];
        #pragma unroll
        for (int e = 0; e < E_; e++) {
            int g = e / EPG_;
            tmp[e] = (g == g1 || g == g2) ? sb[e] : 0.f;
        }
        bool taken[E_];
        #pragma unroll
        for (int e = 0; e < E_; e++) taken[e] = false;
        int ids[TOPK_]; float wv[TOPK_]; float wsum = 0.f;
        #pragma unroll
        for (int k = 0; k < TOPK_; k++) {
            int bi = -1; float bv = -INFINITY;
            for (int e = 0; e < E_; e++) {
                if (!taken[e] && tmp[e] > bv) { bv = tmp[e]; bi = e; }
            }
            taken[bi] = true;
            ids[k] = bi;
            wv[k] = sc[bi];
            wsum += wv[k];
        }
        float inv = 1.f / wsum;
        #pragma unroll
        for (int k = 0; k < TOPK_; k++) {
            int e = ids[k];
            int pos = atomicAdd(&d_cnt[e], 1);
            d_tok[e*T_ + pos] = t;
            d_dst[e*T_ + pos] = t*TOPK_ + k;
            d_wslot[t*TOPK_ + k] = wv[k] * inv;
        }
    }
}

// ---------------- mma / ldmatrix / cp.async helpers ----------------
__device__ __forceinline__ void mma_f16(float c[4], const unsigned a[4], const unsigned b[2]) {
    asm volatile(
        "mma.sync.aligned.m16n8k16.row.col.f32.f16.f16.f32 "
        "{%0,%1,%2,%3}, {%4,%5,%6,%7}, {%8,%9}, {%0,%1,%2,%3};"
        : "+f"(c[0]), "+f"(c[1]), "+f"(c[2]), "+f"(c[3])
        : "r"(a[0]), "r"(a[1]), "r"(a[2]), "r"(a[3]), "r"(b[0]), "r"(b[1]));
}
__device__ __forceinline__ void ldsm4(unsigned &r0, unsigned &r1, unsigned &r2, unsigned &r3,
                                      unsigned addr) {
    asm volatile("ldmatrix.sync.aligned.m8n8.x4.shared.b16 {%0,%1,%2,%3}, [%4];"
                 : "=r"(r0), "=r"(r1), "=r"(r2), "=r"(r3) : "r"(addr));
}
__device__ __forceinline__ void red_add_v2(float* ptr, float v0, float v1) {
    asm volatile("red.global.add.v2.f32 [%0], {%1, %2};"
                 :: "l"(ptr), "f"(v0), "f"(v1) : "memory");
}
__device__ __forceinline__ void cpa16(unsigned dst, const void* src, int sz) {
    asm volatile("cp.async.cg.shared.global [%0], [%1], 16, %2;"
                 :: "r"(dst), "l"(src), "r"(sz) : "memory");
}
__device__ __forceinline__ void cpa_commit() {
    asm volatile("cp.async.commit_group;" ::: "memory");
}
__device__ __forceinline__ void cpa_wait1() {
    asm volatile("cp.async.wait_group 1;" ::: "memory");
}
__device__ __forceinline__ float silu_mul(float g, float u) {
    return (g / (1.f + expf(-g))) * u;
}

#define RS 20   // smem row stride in 32-bit words (word = half2)
// smem layout (dynamic): A stages 0..2, then B stages 0..1. 128 rows each.
#define STAGE_W   (128*RS)          // words per stage
#define STAGE_B   (STAGE_W*4)       // bytes per stage (10240)
#define GSMEM     (5*STAGE_B)       // 51200 bytes

// ============ fused gate_up GEMM + silu*mul*w -> fp16 act ============
// grid (I/64, T/128, E+1). Expert E = shared (weights Sgu, weight 1.0).
// A = d_x16 (fp16) via 3-stage cp.async (2 tiles ahead, wait_group 1).
// B = fp32 weights, LDG+cvt+STS, double-buffered with register prefetch.
// B smem rows interleave gate/up so each thread's mma col pair = (gate j, up j).
__global__ void __launch_bounds__(256, 2)
gu_silu_gemm(const __half* __restrict__ X16,
             const float* __restrict__ Wgu,    // [E,2I,H]
             const float* __restrict__ Sgu,    // [2I,H]
             __half* __restrict__ Act,
             const int* __restrict__ counts,
             const int* __restrict__ tok,
             const int* __restrict__ dst,
             const float* __restrict__ wslot)
{
    const int e = blockIdx.z;
    const int M = counts[e];
    const int m0 = blockIdx.y * 128;
    if (m0 >= M) return;
    const int n0a = blockIdx.x * 64;
    const float* W = (e == E_) ? Sgu : (Wgu + (size_t)e * TWOI_ * H_);
    const int K = H_;

    extern __shared__ unsigned smem[];
    unsigned* Bst[2] = { smem + 3*STAGE_W, smem + 4*STAGE_W };

    const int tid  = threadIdx.x;
    const int lane = tid & 31;
    const int warp = tid >> 5;
    const int wm   = warp >> 1;
    const int wn   = warp & 1;
    const int g    = lane >> 2;
    const int tg   = lane & 3;

    const int lrow = tid >> 1;
    const int kfl  = (tid & 1) * 16;   // element offset within 32-elem slab
    const int kwd  = (tid & 1) * 8;    // word offset within 16-word row

    const bool a_ok = (m0 + lrow) < M;
    const int asz = a_ok ? 16 : 0;
    long arow = 0;
    if (a_ok) arow = (long)tok[e*T_ + m0 + lrow];
    const __half* Ag = X16 + arow * H_ + kfl;
    const long brow = (long)((lrow & 1) * I_ + n0a + (lrow >> 1));
    const float* Bg = W + brow * K + kfl;

    const int ntiles = K >> 5;   // BK = 32

    const unsigned smem0 = (unsigned)__cvta_generic_to_shared(smem);
    const unsigned aB[3] = { smem0, smem0 + STAGE_B, smem0 + 2*STAGE_B };
    const unsigned bB[2] = { smem0 + 3*STAGE_B, smem0 + 4*STAGE_B };
    const unsigned aOff = (unsigned)((lrow*RS + kwd) * 4);

    // prologue: A_0 and A_1 in flight (separate groups), B_0 in regs
    cpa16(aB[0] + aOff,      Ag,     asz);
    cpa16(aB[0] + aOff + 16, Ag + 8, asz);
    cpa_commit();
    cpa16(aB[1] + aOff,      Ag + 32, asz);
    cpa16(aB[1] + aOff + 16, Ag + 40, asz);
    cpa_commit();
    float4 pb[4];
    #pragma unroll
    for (int c = 0; c < 4; c++) pb[c] = *(const float4*)(Bg + c*4);

    float acc[2][8][4];
    #pragma unroll
    for (int mt = 0; mt < 2; mt++)
        #pragma unroll
        for (int nt = 0; nt < 8; nt++)
            #pragma unroll
            for (int i = 0; i < 4; i++) acc[mt][nt][i] = 0.f;

    const int ml = lane >> 3, rl = lane & 7;
    const int a_r = wm*32 + (ml & 1)*8 + rl;
    const int a_w = (ml >> 1) * 4;
    const int b_r = wn*64 + (ml >> 1)*8 + rl;
    const int b_w = (ml & 1) * 4;

    for (int kt = 0; kt < ntiles; kt++) {
        const int ab3 = kt % 3;
        const int bbf = kt & 1;
        // stage B_kt (cvt fp32->fp16x2)
        unsigned* bs = Bst[bbf] + lrow*RS + kwd;
        {
            uint4 w0, w1;
            w0.x = pack_h2(pb[0].x, pb[0].y); w0.y = pack_h2(pb[0].z, pb[0].w);
            w0.z = pack_h2(pb[1].x, pb[1].y); w0.w = pack_h2(pb[1].z, pb[1].w);
            w1.x = pack_h2(pb[2].x, pb[2].y); w1.y = pack_h2(pb[2].z, pb[2].w);
            w1.z = pack_h2(pb[3].x, pb[3].y); w1.w = pack_h2(pb[3].z, pb[3].w);
            *(uint4*)(bs)     = w0;
            *(uint4*)(bs + 4) = w1;
        }
        // prefetch B_{kt+1}
        if (kt + 1 < ntiles) {
            const float* bg = Bg + (kt+1)*32;
            #pragma unroll
            for (int c = 0; c < 4; c++) pb[c] = *(const float4*)(bg + c*4);
        }
        // A_kt must have landed; A_{kt+1} may still be in flight
        cpa_wait1();
        __syncthreads();
        // refill A buffer (kt+2)%3 — its readers (iteration kt-1) retired at this sync
        if (kt + 2 < ntiles) {
            const __half* ag = Ag + (kt+2)*32;
            const unsigned ad = aB[(kt+2) % 3] + aOff;
            cpa16(ad,      ag,     asz);
            cpa16(ad + 16, ag + 8, asz);
        }
        cpa_commit();

        const unsigned ab = aB[ab3];
        const unsigned bb = bB[bbf];
        #pragma unroll
        for (int ks = 0; ks < 2; ks++) {
            const int kw = ks * 8;
            unsigned a[2][4], b[8][2];
            #pragma unroll
            for (int mt = 0; mt < 2; mt++)
                ldsm4(a[mt][0], a[mt][1], a[mt][2], a[mt][3],
                      ab + (unsigned)(((a_r + mt*16)*RS + kw + a_w) * 4));
            #pragma unroll
            for (int p = 0; p < 4; p++)
                ldsm4(b[2*p][0], b[2*p][1], b[2*p+1][0], b[2*p+1][1],
                      bb + (unsigned)(((b_r + p*16)*RS + kw + b_w) * 4));
            #pragma unroll
            for (int mt = 0; mt < 2; mt++)
                #pragma unroll
                for (int nt = 0; nt < 8; nt++)
                    mma_f16(acc[mt][nt], a[mt], b[nt]);
        }
    }

    // epilogue: col pair = (gate j, up j); write fp16 act
    #pragma unroll
    for (int mt = 0; mt < 2; mt++) {
        #pragma unroll
        for (int half = 0; half < 2; half++) {
            int lm = m0 + wm*32 + mt*16 + g + half*8;
            if (lm < M) {
                long crow = (long)dst[e*T_ + lm];
                float w = (crow < NPAIR_) ? wslot[crow] : 1.f;
                __half* Cp = Act + crow * I_ + n0a + wn*32 + tg;
                #pragma unroll
                for (int nt = 0; nt < 8; nt++) {
                    float gv = acc[mt][nt][half*2 + 0];
                    float uv = acc[mt][nt][half*2 + 1];
                    Cp[nt*4] = __float2half_rn(w * silu_mul(gv, uv));
                }
            }
        }
    }
}

// ============ down GEMM ============
// A = fp16 act via 3-stage cp.async. B = fp32 weights, cvt at staging.
// SHARED=true : A rows NPAIR_+m, plain store into out (initializes it).
// SHARED=false: grid.z = expert, gather by slot, red.v2 accumulate 2.5*y.
template<bool SHARED>
__global__ void __launch_bounds__(256, 2)
down_gemm(const __half* __restrict__ Act,
          const float* __restrict__ Wbase,   // SHARED: [H,I], else [E,H,I]
          float* __restrict__ Out,
          const int* __restrict__ counts,
          const int* __restrict__ dst)
{
    const int e = SHARED ? 0 : blockIdx.z;
    const int M = SHARED ? T_ : counts[e];
    const int m0 = blockIdx.y * 128;
    if (m0 >= M) return;
    const int n0 = blockIdx.x * 128;
    const float* W = SHARED ? Wbase : (Wbase + (size_t)e * H_ * I_);
    const int K = I_;

    extern __shared__ unsigned smem[];
    unsigned* Bst[2] = { smem + 3*STAGE_W, smem + 4*STAGE_W };

    const int tid  = threadIdx.x;
    const int lane = tid & 31;
    const int warp = tid >> 5;
    const int wm   = warp >> 1;
    const int wn   = warp & 1;
    const int g    = lane >> 2;
    const int tg   = lane & 3;

    const int lrow = tid >> 1;
    const int kfl  = (tid & 1) * 16;
    const int kwd  = (tid & 1) * 8;

    const bool a_ok = (m0 + lrow) < M;
    const int asz = a_ok ? 16 : 0;
    long arow = 0;
    if (a_ok) arow = SHARED ? (long)(NPAIR_ + m0 + lrow) : (long)dst[e*T_ + m0 + lrow];
    const __half* Ag = Act + arow * I_ + kfl;
    const float* Bg = W + (long)(n0 + lrow) * K + kfl;

    const int ntiles = K >> 5;

    const unsigned smem0 = (unsigned)__cvta_generic_to_shared(smem);
    const unsigned aB[3] = { smem0, smem0 + STAGE_B, smem0 + 2*STAGE_B };
    const unsigned bB[2] = { smem0 + 3*STAGE_B, smem0 + 4*STAGE_B };
    const unsigned aOff = (unsigned)((lrow*RS + kwd) * 4);

    cpa16(aB[0] + aOff,      Ag,     asz);
    cpa16(aB[0] + aOff + 16, Ag + 8, asz);
    cpa_commit();
    cpa16(aB[1] + aOff,      Ag + 32, asz);
    cpa16(aB[1] + aOff + 16, Ag + 40, asz);
    cpa_commit();
    float4 pb[4];
    #pragma unroll
    for (int c = 0; c < 4; c++) pb[c] = *(const float4*)(Bg + c*4);

    float acc[2][8][4];
    #pragma unroll
    for (int mt = 0; mt < 2; mt++)
        #pragma unroll
        for (int nt = 0; nt < 8; nt++)
            #pragma unroll
            for (int i = 0; i < 4; i++) acc[mt][nt][i] = 0.f;

    const int ml = lane >> 3, rl = lane & 7;
    const int a_r = wm*32 + (ml & 1)*8 + rl;
    const int a_w = (ml >> 1) * 4;
    const int b_r = wn*64 + (ml >> 1)*8 + rl;
    const int b_w = (ml & 1) * 4;

    for (int kt = 0; kt < ntiles; kt++) {
        const int ab3 = kt % 3;
        const int bbf = kt & 1;
        unsigned* bs = Bst[bbf] + lrow*RS + kwd;
        {
            uint4 w0, w1;
            w0.x = pack_h2(pb[0].x, pb[0].y); w0.y = pack_h2(pb[0].z, pb[0].w);
            w0.z = pack_h2(pb[1].x, pb[1].y); w0.w = pack_h2(pb[1].z, pb[1].w);
            w1.x = pack_h2(pb[2].x, pb[2].y); w1.y = pack_h2(pb[2].z, pb[2].w);
            w1.z = pack_h2(pb[3].x, pb[3].y); w1.w = pack_h2(pb[3].z, pb[3].w);
            *(uint4*)(bs)     = w0;
            *(uint4*)(bs + 4) = w1;
        }
        if (kt + 1 < ntiles) {
            const float* bg = Bg + (kt+1)*32;
            #pragma unroll
            for (int c = 0; c < 4; c++) pb[c] = *(const float4*)(bg + c*4);
        }
        cpa_wait1();
        __syncthreads();
        if (kt + 2 < ntiles) {
            const __half* ag = Ag + (kt+2)*32;
            const unsigned ad = aB[(kt+2) % 3] + aOff;
            cpa16(ad,      ag,     asz);
            cpa16(ad + 16, ag + 8, asz);
        }
        cpa_commit();

        const unsigned ab = aB[ab3];
        const unsigned bb = bB[bbf];
        #pragma unroll
        for (int ks = 0; ks < 2; ks++) {
            const int kw = ks * 8;
            unsigned a[2][4], b[8][2];
            #pragma unroll
            for (int mt = 0; mt < 2; mt++)
                ldsm4(a[mt][0], a[mt][1], a[mt][2], a[mt][3],
                      ab + (unsigned)(((a_r + mt*16)*RS + kw + a_w) * 4));
            #pragma unroll
            for (int p = 0; p < 4; p++)
                ldsm4(b[2*p][0], b[2*p][1], b[2*p+1][0], b[2*p+1][1],
                      bb + (unsigned)(((b_r + p*16)*RS + kw + b_w) * 4));
            #pragma unroll
            for (int mt = 0; mt < 2; mt++)
                #pragma unroll
                for (int nt = 0; nt < 8; nt++)
                    mma_f16(acc[mt][nt], a[mt], b[nt]);
        }
    }

    #pragma unroll
    for (int mt = 0; mt < 2; mt++) {
        #pragma unroll
        for (int half = 0; half < 2; half++) {
            int lm = m0 + wm*32 + mt*16 + g + half*8;
            if (lm < M) {
                if (SHARED) {
                    float* Cp = Out + (long)lm * H_ + n0 + wn*64 + 2*tg;
                    #pragma unroll
                    for (int nt = 0; nt < 8; nt++) {
                        float2 v;
                        v.x = acc[mt][nt][half*2 + 0];
                        v.y = acc[mt][nt][half*2 + 1];
                        *(float2*)(Cp + nt*8) = v;
                    }
                } else {
                    int slot = dst[e*T_ + lm];
                    float* Cp = Out + (long)(slot >> 2) * H_ + n0 + wn*64 + 2*tg;
                    #pragma unroll
                    for (int nt = 0; nt < 8; nt++) {
                        red_add_v2(Cp + nt*8,
                                   RSCALE_ * acc[mt][nt][half*2 + 0],
                                   RSCALE_ * acc[mt][nt][half*2 + 1]);
                    }
                }
            }
        }
    }
}

// ---------------- launcher ----------------
extern "C" void kernel_launch(void* const* d_in, const int* in_sizes, int n_in,
                              void* d_out, int out_size) {
    const float* x        = (const float*)d_in[0];
    const float* gate_w   = (const float*)d_in[1];
    const float* e_bias   = (const float*)d_in[2];
    const float* w_gu     = (const float*)d_in[3];
    const float* w_dn     = (const float*)d_in[4];
    const float* s_wgu    = (const float*)d_in[5];
    const float* s_wdn    = (const float*)d_in[6];
    float* out = (float*)d_out;

    __half *p_x16, *p_act; float* p_wslot;
    int *p_cnt, *p_tok, *p_dst;
    cudaGetSymbolAddress((void**)&p_x16,   d_x16);
    cudaGetSymbolAddress((void**)&p_act,   d_act);
    cudaGetSymbolAddress((void**)&p_wslot, d_wslot);
    cudaGetSymbolAddress((void**)&p_cnt,   d_cnt);
    cudaGetSymbolAddress((void**)&p_tok,   d_tok);
    cudaGetSymbolAddress((void**)&p_dst,   d_dst);

    // opt-in to 50KB dynamic smem (idempotent host-side attribute)
    cudaFuncSetAttribute(gu_silu_gemm,
                         cudaFuncAttributeMaxDynamicSharedMemorySize, GSMEM);
    cudaFuncSetAttribute(down_gemm<true>,
                         cudaFuncAttributeMaxDynamicSharedMemorySize, GSMEM);
    cudaFuncSetAttribute(down_gemm<false>,
                         cudaFuncAttributeMaxDynamicSharedMemorySize, GSMEM);

    // 1. reset counters + shared-expert gather lists
    init_kernel<<<(T_ + 255)/256, 256>>>();

    // 1b. x -> fp16
    cvt_x_kernel<<<(T_*H_/8 + 255)/256, 256>>>(x);

    // 2. router (fp32 exact)
    router_kernel<<<T_, 512>>>(x, gate_w, e_bias);

    // 3. all gate_up + silu (+w): routed experts AND shared (z = E_)
    gu_silu_gemm<<<dim3(I_/64, T_/128, E_+1), 256, GSMEM>>>(
        p_x16, w_gu, s_wgu, p_act, p_cnt, p_tok, p_dst, p_wslot);

    // 4. shared down: plain store initializes out
    down_gemm<true><<<dim3(H_/128, T_/128, 1), 256, GSMEM>>>(
        p_act, s_wdn, out, p_cnt, p_dst);

    // 5. routed down: red.v2 accumulate 2.5*y into out
    down_gemm<false><<<dim3(H_/128, T_/128, E_), 256, GSMEM>>>(
        p_act, w_dn, out, p_cnt, p_dst);
}

// round 13
// speedup vs baseline: 1.4333x; 1.0016x over previous
#include <cuda_runtime.h>
#include <cuda_fp16.h>
#include <math.h>

// ---------------- problem constants ----------------
#define T_      1024
#define H_      2048
#define I_      1024
#define E_      16            // routed experts; index E_ = shared expert
#define TWOI_   2048
#define G_      4
#define EPG_    4
#define TOPK_   4
#define NPAIR_  (T_*TOPK_)    // 4096 routed slots; shared slots are NPAIR_+t
#define NROWS_  (NPAIR_+T_)   // 5120 act rows
#define RSCALE_ 2.5f

// ---------------- device scratch (no allocations allowed) ----------------
__device__ __half d_x16 [(size_t)T_*H_];       // x converted to fp16
__device__ __half d_act [(size_t)NROWS_*I_];   // silu(g)*u*w, fp16, by slot
__device__ int    d_cnt [E_+1];
__device__ int    d_tok [(E_+1)*T_];           // gather: token per expert entry
__device__ int    d_dst [(E_+1)*T_];           // slot per expert entry
__device__ float  d_wslot[NPAIR_];             // routing weight per routed slot

// ---------------- fp16 pack helper ----------------
__device__ __forceinline__ unsigned pack_h2(float lo, float hi) {
    unsigned r;
    asm("cvt.rn.f16x2.f32 %0, %1, %2;" : "=r"(r) : "f"(hi), "f"(lo));
    return r;
}

// ---------------- cvt x -> fp16 + init counters/shared lists (merged) ----------------
__global__ void cvt_init_kernel(const float* __restrict__ x) {
    int i = blockIdx.x * blockDim.x + threadIdx.x;   // over T_*H_/8 = 262144
    const float4* s = (const float4*)x + (size_t)i*2;
    float4 v0 = s[0], v1 = s[1];
    uint4 o;
    o.x = pack_h2(v0.x, v0.y); o.y = pack_h2(v0.z, v0.w);
    o.z = pack_h2(v1.x, v1.y); o.w = pack_h2(v1.z, v1.w);
    ((uint4*)d_x16)[i] = o;
    if (i < T_) {
        d_tok[E_*T_ + i] = i;
        d_dst[E_*T_ + i] = NPAIR_ + i;
    }
    if (i < E_) d_cnt[i] = 0;
    if (i == E_) d_cnt[E_] = T_;
}

// ---------------- router (fp32 exact, replicates reference grouped top-k) ----------------
// x row cached in smem once per block (16 warps previously re-streamed it).
__global__ void router_kernel(const float* __restrict__ x,
                              const float* __restrict__ gate_w,
                              const float* __restrict__ e_bias) {
    int t = blockIdx.x;
    int warp = threadIdx.x >> 5;
    int lane = threadIdx.x & 31;
    __shared__ float xs[H_];
    const float* xr = x + (size_t)t * H_;
    for (int h = threadIdx.x; h < H_; h += 512) xs[h] = xr[h];
    __syncthreads();
    const float* wr = gate_w + (size_t)warp * H_;
    float s = 0.f;
    for (int h = lane; h < H_; h += 32) s += xs[h] * wr[h];
    #pragma unroll
    for (int o = 16; o; o >>= 1) s += __shfl_xor_sync(0xFFFFFFFFu, s, o);
    __shared__ float logit[E_];
    if (lane == 0) logit[warp] = s;
    __syncthreads();
    if (threadIdx.x == 0) {
        float sc[E_], sb[E_];
        #pragma unroll
        for (int e = 0; e < E_; e++) {
            sc[e] = 1.f / (1.f + expf(-logit[e]));
            sb[e] = sc[e] + e_bias[e];
        }
        float gs[G_];
        #pragma unroll
        for (int g = 0; g < G_; g++) {
            float m1 = -INFINITY, m2 = -INFINITY;
            #pragma unroll
            for (int i = 0; i < EPG_; i++) {
                float v = sb[g*EPG_ + i];
                if (v > m1) { m2 = m1; m1 = v; }
                else if (v > m2) { m2 = v; }
            }
            gs[g] = m1 + m2;
        }
        int g1 = 0;
        for (int g = 1; g < G_; g++) if (gs[g] > gs[g1]) g1 = g;
        int g2 = -1;
        for (int g = 0; g < G_; g++) {
            if (g == g1) continue;
            if (g2 < 0 || gs[g] > gs[g2]) g2 = g;
        }
        float tmp[E_];
        #pragma unroll
        for (int e = 0; e < E_; e++) {
            int g = e / EPG_;
            tmp[e] = (g == g1 || g == g2) ? sb[e] : 0.f;
        }
        bool taken[E_];
        #pragma unroll
        for (int e = 0; e < E_; e++) taken[e] = false;
        int ids[TOPK_]; float wv[TOPK_]; float wsum = 0.f;
        #pragma unroll
        for (int k = 0; k < TOPK_; k++) {
            int bi = -1; float bv = -INFINITY;
            for (int e = 0; e < E_; e++) {
                if (!taken[e] && tmp[e] > bv) { bv = tmp[e]; bi = e; }
            }
            taken[bi] = true;
            ids[k] = bi;
            wv[k] = sc[bi];
            wsum += wv[k];
        }
        float inv = 1.f / wsum;
        #pragma unroll
        for (int k = 0; k < TOPK_; k++) {
            int e = ids[k];
            int pos = atomicAdd(&d_cnt[e], 1);
            d_tok[e*T_ + pos] = t;
            d_dst[e*T_ + pos] = t*TOPK_ + k;
            d_wslot[t*TOPK_ + k] = wv[k] * inv;
        }
    }
}

// ---------------- mma / ldmatrix / cp.async helpers ----------------
__device__ __forceinline__ void mma_f16(float c[4], const unsigned a[4], const unsigned b[2]) {
    asm volatile(
        "mma.sync.aligned.m16n8k16.row.col.f32.f16.f16.f32 "
        "{%0,%1,%2,%3}, {%4,%5,%6,%7}, {%8,%9}, {%0,%1,%2,%3};"
        : "+f"(c[0]), "+f"(c[1]), "+f"(c[2]), "+f"(c[3])
        : "r"(a[0]), "r"(a[1]), "r"(a[2]), "r"(a[3]), "r"(b[0]), "r"(b[1]));
}
__device__ __forceinline__ void ldsm4(unsigned &r0, unsigned &r1, unsigned &r2, unsigned &r3,
                                      unsigned addr) {
    asm volatile("ldmatrix.sync.aligned.m8n8.x4.shared.b16 {%0,%1,%2,%3}, [%4];"
                 : "=r"(r0), "=r"(r1), "=r"(r2), "=r"(r3) : "r"(addr));
}
__device__ __forceinline__ void red_add_v2(float* ptr, float v0, float v1) {
    asm volatile("red.global.add.v2.f32 [%0], {%1, %2};"
                 :: "l"(ptr), "f"(v0), "f"(v1) : "memory");
}
__device__ __forceinline__ void cpa16(unsigned dst, const void* src, int sz) {
    asm volatile("cp.async.cg.shared.global [%0], [%1], 16, %2;"
                 :: "r"(dst), "l"(src), "r"(sz) : "memory");
}
__device__ __forceinline__ void cpa_commit() {
    asm volatile("cp.async.commit_group;" ::: "memory");
}
__device__ __forceinline__ void cpa_wait0() {
    asm volatile("cp.async.wait_group 0;" ::: "memory");
}
__device__ __forceinline__ float silu_mul(float g, float u) {
    return (g / (1.f + expf(-g))) * u;
}

#define RS 20   // smem row stride in 32-bit words (word = half2)

// ============ fused gate_up GEMM + silu*mul*w -> fp16 act ============
// grid (I/64, T/128, E+1). Expert E = shared (weights Sgu, weight 1.0).
// A = d_x16 (fp16) staged via cp.async. B = fp32 weights, cvt at staging.
// B smem rows interleave gate/up so each thread's mma col pair = (gate j, up j).
__global__ void __launch_bounds__(256, 2)
gu_silu_gemm(const __half* __restrict__ X16,
             const float* __restrict__ Wgu,    // [E,2I,H]
             const float* __restrict__ Sgu,    // [2I,H]
             __half* __restrict__ Act,
             const int* __restrict__ counts,
             const int* __restrict__ tok,
             const int* __restrict__ dst,
             const float* __restrict__ wslot)
{
    const int e = blockIdx.z;
    const int M = counts[e];
    const int m0 = blockIdx.y * 128;
    if (m0 >= M) return;
    const int n0a = blockIdx.x * 64;
    const float* W = (e == E_) ? Sgu : (Wgu + (size_t)e * TWOI_ * H_);
    const int K = H_;

    __shared__ unsigned As[2][128*RS];
    __shared__ unsigned Bs[2][128*RS];

    const int tid  = threadIdx.x;
    const int lane = tid & 31;
    const int warp = tid >> 5;
    const int wm   = warp >> 1;
    const int wn   = warp & 1;
    const int g    = lane >> 2;
    const int tg   = lane & 3;

    const int lrow = tid >> 1;
    const int kfl  = (tid & 1) * 16;   // element offset within 32-elem slab
    const int kwd  = (tid & 1) * 8;    // word offset within 16-word row

    const bool a_ok = (m0 + lrow) < M;
    const int asz = a_ok ? 16 : 0;
    long arow = 0;
    if (a_ok) arow = (long)tok[e*T_ + m0 + lrow];
    const __half* Ag = X16 + arow * H_ + kfl;          // fp16 source
    const long brow = (long)((lrow & 1) * I_ + n0a + (lrow >> 1));
    const float* Bg = W + brow * K + kfl;

    const int ntiles = K >> 5;   // BK = 32

    const unsigned aBuf[2] = { (unsigned)__cvta_generic_to_shared(As[0]),
                               (unsigned)__cvta_generic_to_shared(As[1]) };
    const unsigned bBuf[2] = { (unsigned)__cvta_generic_to_shared(Bs[0]),
                               (unsigned)__cvta_generic_to_shared(Bs[1]) };
    const unsigned aDst0 = aBuf[0] + (unsigned)((lrow*RS + kwd) * 4);
    const unsigned aDst1 = aBuf[1] + (unsigned)((lrow*RS + kwd) * 4);

    // prologue: A_0 via cp.async, B_0 into regs
    cpa16(aDst0,      Ag,     asz);
    cpa16(aDst0 + 16, Ag + 8, asz);
    cpa_commit();
    float4 pb[4];
    #pragma unroll
    for (int c = 0; c < 4; c++) pb[c] = *(const float4*)(Bg + c*4);

    float acc[2][8][4];
    #pragma unroll
    for (int mt = 0; mt < 2; mt++)
        #pragma unroll
        for (int nt = 0; nt < 8; nt++)
            #pragma unroll
            for (int i = 0; i < 4; i++) acc[mt][nt][i] = 0.f;

    const int ml = lane >> 3, rl = lane & 7;
    const int a_r = wm*32 + (ml & 1)*8 + rl;
    const int a_w = (ml >> 1) * 4;
    const int b_r = wn*64 + (ml >> 1)*8 + rl;
    const int b_w = (ml & 1) * 4;

    for (int kt = 0; kt < ntiles; kt++) {
        const int buf = kt & 1;
        // stage B_kt (cvt fp32->fp16x2)
        unsigned* bs = &Bs[buf][lrow*RS + kwd];
        {
            uint4 w0, w1;
            w0.x = pack_h2(pb[0].x, pb[0].y); w0.y = pack_h2(pb[0].z, pb[0].w);
            w0.z = pack_h2(pb[1].x, pb[1].y); w0.w = pack_h2(pb[1].z, pb[1].w);
            w1.x = pack_h2(pb[2].x, pb[2].y); w1.y = pack_h2(pb[2].z, pb[2].w);
            w1.z = pack_h2(pb[3].x, pb[3].y); w1.w = pack_h2(pb[3].z, pb[3].w);
            *(uint4*)(bs)     = w0;
            *(uint4*)(bs + 4) = w1;
        }
        // prefetch B_{kt+1}
        if (kt + 1 < ntiles) {
            const float* bg = Bg + (kt+1)*32;
            #pragma unroll
            for (int c = 0; c < 4; c++) pb[c] = *(const float4*)(bg + c*4);
        }
        // A_kt must have landed (issued after previous sync / prologue)
        cpa_wait0();
        __syncthreads();
        // safe to refill the other buffer now: all warps finished reading it
        if (kt + 1 < ntiles) {
            const __half* ag = Ag + (kt+1)*32;
            const unsigned ad = (buf ? aDst0 : aDst1);
            cpa16(ad,      ag,     asz);
            cpa16(ad + 16, ag + 8, asz);
        }
        cpa_commit();

        const unsigned ab = aBuf[buf];
        const unsigned bb = bBuf[buf];
        #pragma unroll
        for (int ks = 0; ks < 2; ks++) {
            const int kw = ks * 8;
            unsigned a[2][4], b[8][2];
            #pragma unroll
            for (int mt = 0; mt < 2; mt++)
                ldsm4(a[mt][0], a[mt][1], a[mt][2], a[mt][3],
                      ab + (unsigned)(((a_r + mt*16)*RS + kw + a_w) * 4));
            #pragma unroll
            for (int p = 0; p < 4; p++)
                ldsm4(b[2*p][0], b[2*p][1], b[2*p+1][0], b[2*p+1][1],
                      bb + (unsigned)(((b_r + p*16)*RS + kw + b_w) * 4));
            #pragma unroll
            for (int mt = 0; mt < 2; mt++)
                #pragma unroll
                for (int nt = 0; nt < 8; nt++)
                    mma_f16(acc[mt][nt], a[mt], b[nt]);
        }
    }

    // epilogue: col pair = (gate j, up j); write fp16 act
    #pragma unroll
    for (int mt = 0; mt < 2; mt++) {
        #pragma unroll
        for (int half = 0; half < 2; half++) {
            int lm = m0 + wm*32 + mt*16 + g + half*8;
            if (lm < M) {
                long crow = (long)dst[e*T_ + lm];
                float w = (crow < NPAIR_) ? wslot[crow] : 1.f;
                __half* Cp = Act + crow * I_ + n0a + wn*32 + tg;
                #pragma unroll
                for (int nt = 0; nt < 8; nt++) {
                    float gv = acc[mt][nt][half*2 + 0];
                    float uv = acc[mt][nt][half*2 + 1];
                    Cp[nt*4] = __float2half_rn(w * silu_mul(gv, uv));
                }
            }
        }
    }
}

// ============ down GEMM ============
// A = fp16 act staged via cp.async. B = fp32 weights, cvt at staging.
// SHARED=true : A rows NPAIR_+m, plain store into out (initializes it).
// SHARED=false: grid.z = expert, gather by slot, red.v2 accumulate 2.5*y.
template<bool SHARED>
__global__ void __launch_bounds__(256, 2)
down_gemm(const __half* __restrict__ Act,
          const float* __restrict__ Wbase,   // SHARED: [H,I], else [E,H,I]
          float* __restrict__ Out,
          const int* __restrict__ counts,
          const int* __restrict__ dst)
{
    const int e = SHARED ? 0 : blockIdx.z;
    const int M = SHARED ? T_ : counts[e];
    const int m0 = blockIdx.y * 128;
    if (m0 >= M) return;
    const int n0 = blockIdx.x * 128;
    const float* W = SHARED ? Wbase : (Wbase + (size_t)e * H_ * I_);
    const int K = I_;

    __shared__ unsigned As[2][128*RS];
    __shared__ unsigned Bs[2][128*RS];

    const int tid  = threadIdx.x;
    const int lane = tid & 31;
    const int warp = tid >> 5;
    const int wm   = warp >> 1;
    const int wn   = warp & 1;
    const int g    = lane >> 2;
    const int tg   = lane & 3;

    const int lrow = tid >> 1;
    const int kfl  = (tid & 1) * 16;
    const int kwd  = (tid & 1) * 8;

    const bool a_ok = (m0 + lrow) < M;
    const int asz = a_ok ? 16 : 0;
    long arow = 0;
    if (a_ok) arow = SHARED ? (long)(NPAIR_ + m0 + lrow) : (long)dst[e*T_ + m0 + lrow];
    const __half* Ag = Act + arow * I_ + kfl;
    const float* Bg = W + (long)(n0 + lrow) * K + kfl;

    const int ntiles = K >> 5;

    const unsigned aBuf[2] = { (unsigned)__cvta_generic_to_shared(As[0]),
                               (unsigned)__cvta_generic_to_shared(As[1]) };
    const unsigned bBuf[2] = { (unsigned)__cvta_generic_to_shared(Bs[0]),
                               (unsigned)__cvta_generic_to_shared(Bs[1]) };
    const unsigned aDst0 = aBuf[0] + (unsigned)((lrow*RS + kwd) * 4);
    const unsigned aDst1 = aBuf[1] + (unsigned)((lrow*RS + kwd) * 4);

    cpa16(aDst0,      Ag,     asz);
    cpa16(aDst0 + 16, Ag + 8, asz);
    cpa_commit();
    float4 pb[4];
    #pragma unroll
    for (int c = 0; c < 4; c++) pb[c] = *(const float4*)(Bg + c*4);

    float acc[2][8][4];
    #pragma unroll
    for (int mt = 0; mt < 2; mt++)
        #pragma unroll
        for (int nt = 0; nt < 8; nt++)
            #pragma unroll
            for (int i = 0; i < 4; i++) acc[mt][nt][i] = 0.f;

    const int ml = lane >> 3, rl = lane & 7;
    const int a_r = wm*32 + (ml & 1)*8 + rl;
    const int a_w = (ml >> 1) * 4;
    const int b_r = wn*64 + (ml >> 1)*8 + rl;
    const int b_w = (ml & 1) * 4;

    for (int kt = 0; kt < ntiles; kt++) {
        const int buf = kt & 1;
        unsigned* bs = &Bs[buf][lrow*RS + kwd];
        {
            uint4 w0, w1;
            w0.x = pack_h2(pb[0].x, pb[0].y); w0.y = pack_h2(pb[0].z, pb[0].w);
            w0.z = pack_h2(pb[1].x, pb[1].y); w0.w = pack_h2(pb[1].z, pb[1].w);
            w1.x = pack_h2(pb[2].x, pb[2].y); w1.y = pack_h2(pb[2].z, pb[2].w);
            w1.z = pack_h2(pb[3].x, pb[3].y); w1.w = pack_h2(pb[3].z, pb[3].w);
            *(uint4*)(bs)     = w0;
            *(uint4*)(bs + 4) = w1;
        }
        if (kt + 1 < ntiles) {
            const float* bg = Bg + (kt+1)*32;
            #pragma unroll
            for (int c = 0; c < 4; c++) pb[c] = *(const float4*)(bg + c*4);
        }
        cpa_wait0();
        __syncthreads();
        if (kt + 1 < ntiles) {
            const __half* ag = Ag + (kt+1)*32;
            const unsigned ad = (buf ? aDst0 : aDst1);
            cpa16(ad,      ag,     asz);
            cpa16(ad + 16, ag + 8, asz);
        }
        cpa_commit();

        const unsigned ab = aBuf[buf];
        const unsigned bb = bBuf[buf];
        #pragma unroll
        for (int ks = 0; ks < 2; ks++) {
            const int kw = ks * 8;
            unsigned a[2][4], b[8][2];
            #pragma unroll
            for (int mt = 0; mt < 2; mt++)
                ldsm4(a[mt][0], a[mt][1], a[mt][2], a[mt][3],
                      ab + (unsigned)(((a_r + mt*16)*RS + kw + a_w) * 4));
            #pragma unroll
            for (int p = 0; p < 4; p++)
                ldsm4(b[2*p][0], b[2*p][1], b[2*p+1][0], b[2*p+1][1],
                      bb + (unsigned)(((b_r + p*16)*RS + kw + b_w) * 4));
            #pragma unroll
            for (int mt = 0; mt < 2; mt++)
                #pragma unroll
                for (int nt = 0; nt < 8; nt++)
                    mma_f16(acc[mt][nt], a[mt], b[nt]);
        }
    }

    #pragma unroll
    for (int mt = 0; mt < 2; mt++) {
        #pragma unroll
        for (int half = 0; half < 2; half++) {
            int lm = m0 + wm*32 + mt*16 + g + half*8;
            if (lm < M) {
                if (SHARED) {
                    float* Cp = Out + (long)lm * H_ + n0 + wn*64 + 2*tg;
                    #pragma unroll
                    for (int nt = 0; nt < 8; nt++) {
                        float2 v;
                        v.x = acc[mt][nt][half*2 + 0];
                        v.y = acc[mt][nt][half*2 + 1];
                        *(float2*)(Cp + nt*8) = v;
                    }
                } else {
                    int slot = dst[e*T_ + lm];
                    float* Cp = Out + (long)(slot >> 2) * H_ + n0 + wn*64 + 2*tg;
                    #pragma unroll
                    for (int nt = 0; nt < 8; nt++) {
                        red_add_v2(Cp + nt*8,
                                   RSCALE_ * acc[mt][nt][half*2 + 0],
                                   RSCALE_ * acc[mt][nt][half*2 + 1]);
                    }
                }
            }
        }
    }
}

// ---------------- launcher ----------------
extern "C" void kernel_launch(void* const* d_in, const int* in_sizes, int n_in,
                              void* d_out, int out_size) {
    const float* x        = (const float*)d_in[0];
    const float* gate_w   = (const float*)d_in[1];
    const float* e_bias   = (const float*)d_in[2];
    const float* w_gu     = (const float*)d_in[3];
    const float* w_dn     = (const float*)d_in[4];
    const float* s_wgu    = (const float*)d_in[5];
    const float* s_wdn    = (const float*)d_in[6];
    float* out = (float*)d_out;

    __half *p_x16, *p_act; float* p_wslot;
    int *p_cnt, *p_tok, *p_dst;
    cudaGetSymbolAddress((void**)&p_x16,   d_x16);
    cudaGetSymbolAddress((void**)&p_act,   d_act);
    cudaGetSymbolAddress((void**)&p_wslot, d_wslot);
    cudaGetSymbolAddress((void**)&p_cnt,   d_cnt);
    cudaGetSymbolAddress((void**)&p_tok,   d_tok);
    cudaGetSymbolAddress((void**)&p_dst,   d_dst);

    // 1. x -> fp16 + counter reset + shared-expert gather lists (merged)
    cvt_init_kernel<<<(T_*H_/8 + 255)/256, 256>>>(x);

    // 2. router (fp32 exact)
    router_kernel<<<T_, 512>>>(x, gate_w, e_bias);

    // 3. all gate_up + silu (+w): routed experts AND shared (z = E_)
    gu_silu_gemm<<<dim3(I_/64, T_/128, E_+1), 256>>>(
        p_x16, w_gu, s_wgu, p_act, p_cnt, p_tok, p_dst, p_wslot);

    // 4. shared down: plain store initializes out
    down_gemm<true><<<dim3(H_/128, T_/128, 1), 256>>>(
        p_act, s_wdn, out, p_cnt, p_dst);

    // 5. routed down: red.v2 accumulate 2.5*y into out
    down_gemm<false><<<dim3(H_/128, T_/128, E_), 256>>>(
        p_act, w_dn, out, p_cnt, p_dst);
}

// round 14
// speedup vs baseline: 1.5159x; 1.0576x over previous
#include <cuda_runtime.h>
#include <cuda_fp16.h>
#include <math.h>

// ---------------- problem constants ----------------
#define T_      1024
#define H_      2048
#define I_      1024
#define E_      16            // routed experts; index E_ = shared expert
#define TWOI_   2048
#define G_      4
#define EPG_    4
#define TOPK_   4
#define NPAIR_  (T_*TOPK_)    // 4096 routed slots; shared slots are NPAIR_+t
#define NROWS_  (NPAIR_+T_)   // 5120 act rows
#define RSCALE_ 2.5f

// ---------------- device scratch (no allocations allowed) ----------------
__device__ __half d_x16 [(size_t)T_*H_];       // x converted to fp16
__device__ __half d_act [(size_t)NROWS_*I_];   // silu(g)*u*w, fp16, by slot
__device__ int    d_cnt [E_+1];
__device__ int    d_tok [(E_+1)*T_];           // gather: token per expert entry
__device__ int    d_dst [(E_+1)*T_];           // slot per expert entry
__device__ float  d_wslot[NPAIR_];             // routing weight per routed slot

// ---------------- fp16 pack helper ----------------
__device__ __forceinline__ unsigned pack_h2(float lo, float hi) {
    unsigned r;
    asm("cvt.rn.f16x2.f32 %0, %1, %2;" : "=r"(r) : "f"(hi), "f"(lo));
    return r;
}

// ---------------- init: reset counters, build shared-expert lists ----------------
__global__ void init_kernel() {
    int idx = blockIdx.x * blockDim.x + threadIdx.x;
    if (idx < T_) {
        d_tok[E_*T_ + idx] = idx;
        d_dst[E_*T_ + idx] = NPAIR_ + idx;
    }
    if (idx < E_) d_cnt[idx] = 0;
    if (idx == E_) d_cnt[E_] = T_;
}

// ---------------- x -> fp16 (8 elems/thread) ----------------
__global__ void cvt_x_kernel(const float* __restrict__ x) {
    int i = blockIdx.x * blockDim.x + threadIdx.x;   // over T_*H_/8
    const float4* s = (const float4*)x + (size_t)i*2;
    float4 v0 = s[0], v1 = s[1];
    uint4 o;
    o.x = pack_h2(v0.x, v0.y); o.y = pack_h2(v0.z, v0.w);
    o.z = pack_h2(v1.x, v1.y); o.w = pack_h2(v1.z, v1.w);
    ((uint4*)d_x16)[i] = o;
}

// ---------------- router (fp32 exact, replicates reference grouped top-k) ----------------
__global__ void router_kernel(const float* __restrict__ x,
                              const float* __restrict__ gate_w,
                              const float* __restrict__ e_bias) {
    int t = blockIdx.x;
    int warp = threadIdx.x >> 5;
    int lane = threadIdx.x & 31;
    const float* xr = x + (size_t)t * H_;
    const float* wr = gate_w + (size_t)warp * H_;
    float s = 0.f;
    for (int h = lane; h < H_; h += 32) s += xr[h] * wr[h];
    #pragma unroll
    for (int o = 16; o; o >>= 1) s += __shfl_xor_sync(0xFFFFFFFFu, s, o);
    __shared__ float logit[E_];
    if (lane == 0) logit[warp] = s;
    __syncthreads();
    if (threadIdx.x == 0) {
        float sc[E_], sb[E_];
        #pragma unroll
        for (int e = 0; e < E_; e++) {
            sc[e] = 1.f / (1.f + expf(-logit[e]));
            sb[e] = sc[e] + e_bias[e];
        }
        float gs[G_];
        #pragma unroll
        for (int g = 0; g < G_; g++) {
            float m1 = -INFINITY, m2 = -INFINITY;
            #pragma unroll
            for (int i = 0; i < EPG_; i++) {
                float v = sb[g*EPG_ + i];
                if (v > m1) { m2 = m1; m1 = v; }
                else if (v > m2) { m2 = v; }
            }
            gs[g] = m1 + m2;
        }
        int g1 = 0;
        for (int g = 1; g < G_; g++) if (gs[g] > gs[g1]) g1 = g;
        int g2 = -1;
        for (int g = 0; g < G_; g++) {
            if (g == g1) continue;
            if (g2 < 0 || gs[g] > gs[g2]) g2 = g;
        }
        float tmp[E_];
        #pragma unroll
        for (int e = 0; e < E_; e++) {
            int g = e / EPG_;
            tmp[e] = (g == g1 || g == g2) ? sb[e] : 0.f;
        }
        bool taken[E_];
        #pragma unroll
        for (int e = 0; e < E_; e++) taken[e] = false;
        int ids[TOPK_]; float wv[TOPK_]; float wsum = 0.f;
        #pragma unroll
        for (int k = 0; k < TOPK_; k++) {
            int bi = -1; float bv = -INFINITY;
            for (int e = 0; e < E_; e++) {
                if (!taken[e] && tmp[e] > bv) { bv = tmp[e]; bi = e; }
            }
            taken[bi] = true;
            ids[k] = bi;
            wv[k] = sc[bi];
            wsum += wv[k];
        }
        float inv = 1.f / wsum;
        #pragma unroll
        for (int k = 0; k < TOPK_; k++) {
            int e = ids[k];
            int pos = atomicAdd(&d_cnt[e], 1);
            d_tok[e*T_ + pos] = t;
            d_dst[e*T_ + pos] = t*TOPK_ + k;
            d_wslot[t*TOPK_ + k] = wv[k] * inv;
        }
    }
}

// ---------------- mma / ldmatrix / cp.async helpers ----------------
__device__ __forceinline__ void mma_f16(float c[4], const unsigned a[4], const unsigned b[2]) {
    asm volatile(
        "mma.sync.aligned.m16n8k16.row.col.f32.f16.f16.f32 "
        "{%0,%1,%2,%3}, {%4,%5,%6,%7}, {%8,%9}, {%0,%1,%2,%3};"
        : "+f"(c[0]), "+f"(c[1]), "+f"(c[2]), "+f"(c[3])
        : "r"(a[0]), "r"(a[1]), "r"(a[2]), "r"(a[3]), "r"(b[0]), "r"(b[1]));
}
__device__ __forceinline__ void ldsm4(unsigned &r0, unsigned &r1, unsigned &r2, unsigned &r3,
                                      unsigned addr) {
    asm volatile("ldmatrix.sync.aligned.m8n8.x4.shared.b16 {%0,%1,%2,%3}, [%4];"
                 : "=r"(r0), "=r"(r1), "=r"(r2), "=r"(r3) : "r"(addr));
}
__device__ __forceinline__ void red_add_v2(float* ptr, float v0, float v1) {
    asm volatile("red.global.add.v2.f32 [%0], {%1, %2};"
                 :: "l"(ptr), "f"(v0), "f"(v1) : "memory");
}
__device__ __forceinline__ void cpa16(unsigned dst, const void* src, int sz) {
    asm volatile("cp.async.cg.shared.global [%0], [%1], 16, %2;"
                 :: "r"(dst), "l"(src), "r"(sz) : "memory");
}
__device__ __forceinline__ void cpa_commit() {
    asm volatile("cp.async.commit_group;" ::: "memory");
}
__device__ __forceinline__ void cpa_wait0() {
    asm volatile("cp.async.wait_group 0;" ::: "memory");
}
__device__ __forceinline__ float silu_mul(float g, float u) {
    return (g / (1.f + expf(-g))) * u;
}

#define RS 20   // smem row stride in 32-bit words (word = half2)

// ============ fused gate_up GEMM + silu*mul*w -> fp16 act ============
// grid (I/64, T/128, E+1). Expert E = shared (weights Sgu, weight 1.0).
// A = d_x16 (fp16) staged via cp.async. B = fp32 weights, cvt at staging.
// B smem rows interleave gate/up so each thread's mma col pair = (gate j, up j).
__global__ void __launch_bounds__(256, 2)
gu_silu_gemm(const __half* __restrict__ X16,
             const float* __restrict__ Wgu,    // [E,2I,H]
             const float* __restrict__ Sgu,    // [2I,H]
             __half* __restrict__ Act,
             const int* __restrict__ counts,
             const int* __restrict__ tok,
             const int* __restrict__ dst,
             const float* __restrict__ wslot)
{
    const int e = blockIdx.z;
    const int M = counts[e];
    const int m0 = blockIdx.y * 128;
    if (m0 >= M) return;
    const int n0a = blockIdx.x * 64;
    const float* W = (e == E_) ? Sgu : (Wgu + (size_t)e * TWOI_ * H_);
    const int K = H_;

    __shared__ unsigned As[2][128*RS];
    __shared__ unsigned Bs[2][128*RS];

    const int tid  = threadIdx.x;
    const int lane = tid & 31;
    const int warp = tid >> 5;
    const int wm   = warp >> 1;
    const int wn   = warp & 1;
    const int g    = lane >> 2;
    const int tg   = lane & 3;

    const int lrow = tid >> 1;
    const int kfl  = (tid & 1) * 16;   // element offset within 32-elem slab
    const int kwd  = (tid & 1) * 8;    // word offset within 16-word row

    const bool a_ok = (m0 + lrow) < M;
    const int asz = a_ok ? 16 : 0;
    long arow = 0;
    if (a_ok) arow = (long)tok[e*T_ + m0 + lrow];
    const __half* Ag = X16 + arow * H_ + kfl;          // fp16 source
    const long brow = (long)((lrow & 1) * I_ + n0a + (lrow >> 1));
    const float* Bg = W + brow * K + kfl;

    const int ntiles = K >> 5;   // BK = 32

    const unsigned aBuf[2] = { (unsigned)__cvta_generic_to_shared(As[0]),
                               (unsigned)__cvta_generic_to_shared(As[1]) };
    const unsigned bBuf[2] = { (unsigned)__cvta_generic_to_shared(Bs[0]),
                               (unsigned)__cvta_generic_to_shared(Bs[1]) };
    const unsigned aDst0 = aBuf[0] + (unsigned)((lrow*RS + kwd) * 4);
    const unsigned aDst1 = aBuf[1] + (unsigned)((lrow*RS + kwd) * 4);

    // prologue: A_0 via cp.async, B_0 into regs
    cpa16(aDst0,      Ag,     asz);
    cpa16(aDst0 + 16, Ag + 8, asz);
    cpa_commit();
    float4 pb[4];
    #pragma unroll
    for (int c = 0; c < 4; c++) pb[c] = *(const float4*)(Bg + c*4);

    float acc[2][8][4];
    #pragma unroll
    for (int mt = 0; mt < 2; mt++)
        #pragma unroll
        for (int nt = 0; nt < 8; nt++)
            #pragma unroll
            for (int i = 0; i < 4; i++) acc[mt][nt][i] = 0.f;

    const int ml = lane >> 3, rl = lane & 7;
    const int a_r = wm*32 + (ml & 1)*8 + rl;
    const int a_w = (ml >> 1) * 4;
    const int b_r = wn*64 + (ml >> 1)*8 + rl;
    const int b_w = (ml & 1) * 4;

    for (int kt = 0; kt < ntiles; kt++) {
        const int buf = kt & 1;
        // stage B_kt (cvt fp32->fp16x2)
        unsigned* bs = &Bs[buf][lrow*RS + kwd];
        {
            uint4 w0, w1;
            w0.x = pack_h2(pb[0].x, pb[0].y); w0.y = pack_h2(pb[0].z, pb[0].w);
            w0.z = pack_h2(pb[1].x, pb[1].y); w0.w = pack_h2(pb[1].z, pb[1].w);
            w1.x = pack_h2(pb[2].x, pb[2].y); w1.y = pack_h2(pb[2].z, pb[2].w);
            w1.z = pack_h2(pb[3].x, pb[3].y); w1.w = pack_h2(pb[3].z, pb[3].w);
            *(uint4*)(bs)     = w0;
            *(uint4*)(bs + 4) = w1;
        }
        // prefetch B_{kt+1}
        if (kt + 1 < ntiles) {
            const float* bg = Bg + (kt+1)*32;
            #pragma unroll
            for (int c = 0; c < 4; c++) pb[c] = *(const float4*)(bg + c*4);
        }
        // A_kt must have landed (issued after previous sync / prologue)
        cpa_wait0();
        __syncthreads();
        // safe to refill the other buffer now: all warps finished reading it
        if (kt + 1 < ntiles) {
            const __half* ag = Ag + (kt+1)*32;
            const unsigned ad = (buf ? aDst0 : aDst1);
            cpa16(ad,      ag,     asz);
            cpa16(ad + 16, ag + 8, asz);
        }
        cpa_commit();

        const unsigned ab = aBuf[buf];
        const unsigned bb = bBuf[buf];
        #pragma unroll
        for (int ks = 0; ks < 2; ks++) {
            const int kw = ks * 8;
            unsigned a[2][4], b[8][2];
            #pragma unroll
            for (int mt = 0; mt < 2; mt++)
                ldsm4(a[mt][0], a[mt][1], a[mt][2], a[mt][3],
                      ab + (unsigned)(((a_r + mt*16)*RS + kw + a_w) * 4));
            #pragma unroll
            for (int p = 0; p < 4; p++)
                ldsm4(b[2*p][0], b[2*p][1], b[2*p+1][0], b[2*p+1][1],
                      bb + (unsigned)(((b_r + p*16)*RS + kw + b_w) * 4));
            #pragma unroll
            for (int mt = 0; mt < 2; mt++)
                #pragma unroll
                for (int nt = 0; nt < 8; nt++)
                    mma_f16(acc[mt][nt], a[mt], b[nt]);
        }
    }

    // epilogue: col pair = (gate j, up j); write fp16 act
    #pragma unroll
    for (int mt = 0; mt < 2; mt++) {
        #pragma unroll
        for (int half = 0; half < 2; half++) {
            int lm = m0 + wm*32 + mt*16 + g + half*8;
            if (lm < M) {
                long crow = (long)dst[e*T_ + lm];
                float w = (crow < NPAIR_) ? wslot[crow] : 1.f;
                __half* Cp = Act + crow * I_ + n0a + wn*32 + tg;
                #pragma unroll
                for (int nt = 0; nt < 8; nt++) {
                    float gv = acc[mt][nt][half*2 + 0];
                    float uv = acc[mt][nt][half*2 + 1];
                    Cp[nt*4] = __float2half_rn(w * silu_mul(gv, uv));
                }
            }
        }
    }
}

// ============ down GEMM ============
// A = fp16 act staged via cp.async. B = fp32 weights, cvt at staging.
// SHARED=true : A rows NPAIR_+m, plain store into out (initializes it).
// SHARED=false: grid.z = expert, gather by slot, red.v2 accumulate 2.5*y.
template<bool SHARED>
__global__ void __launch_bounds__(256, 2)
down_gemm(const __half* __restrict__ Act,
          const float* __restrict__ Wbase,   // SHARED: [H,I], else [E,H,I]
          float* __restrict__ Out,
          const int* __restrict__ counts,
          const int* __restrict__ dst)
{
    const int e = SHARED ? 0 : blockIdx.z;
    const int M = SHARED ? T_ : counts[e];
    const int m0 = blockIdx.y * 128;
    if (m0 >= M) return;
    const int n0 = blockIdx.x * 128;
    const float* W = SHARED ? Wbase : (Wbase + (size_t)e * H_ * I_);
    const int K = I_;

    __shared__ unsigned As[2][128*RS];
    __shared__ unsigned Bs[2][128*RS];

    const int tid  = threadIdx.x;
    const int lane = tid & 31;
    const int warp = tid >> 5;
    const int wm   = warp >> 1;
    const int wn   = warp & 1;
    const int g    = lane >> 2;
    const int tg   = lane & 3;

    const int lrow = tid >> 1;
    const int kfl  = (tid & 1) * 16;
    const int kwd  = (tid & 1) * 8;

    const bool a_ok = (m0 + lrow) < M;
    const int asz = a_ok ? 16 : 0;
    long arow = 0;
    if (a_ok) arow = SHARED ? (long)(NPAIR_ + m0 + lrow) : (long)dst[e*T_ + m0 + lrow];
    const __half* Ag = Act + arow * I_ + kfl;
    const float* Bg = W + (long)(n0 + lrow) * K + kfl;

    const int ntiles = K >> 5;

    const unsigned aBuf[2] = { (unsigned)__cvta_generic_to_shared(As[0]),
                               (unsigned)__cvta_generic_to_shared(As[1]) };
    const unsigned bBuf[2] = { (unsigned)__cvta_generic_to_shared(Bs[0]),
                               (unsigned)__cvta_generic_to_shared(Bs[1]) };
    const unsigned aDst0 = aBuf[0] + (unsigned)((lrow*RS + kwd) * 4);
    const unsigned aDst1 = aBuf[1] + (unsigned)((lrow*RS + kwd) * 4);

    cpa16(aDst0,      Ag,     asz);
    cpa16(aDst0 + 16, Ag + 8, asz);
    cpa_commit();
    float4 pb[4];
    #pragma unroll
    for (int c = 0; c < 4; c++) pb[c] = *(const float4*)(Bg + c*4);

    float acc[2][8][4];
    #pragma unroll
    for (int mt = 0; mt < 2; mt++)
        #pragma unroll
        for (int nt = 0; nt < 8; nt++)
            #pragma unroll
            for (int i = 0; i < 4; i++) acc[mt][nt][i] = 0.f;

    const int ml = lane >> 3, rl = lane & 7;
    const int a_r = wm*32 + (ml & 1)*8 + rl;
    const int a_w = (ml >> 1) * 4;
    const int b_r = wn*64 + (ml >> 1)*8 + rl;
    const int b_w = (ml & 1) * 4;

    for (int kt = 0; kt < ntiles; kt++) {
        const int buf = kt & 1;
        unsigned* bs = &Bs[buf][lrow*RS + kwd];
        {
            uint4 w0, w1;
            w0.x = pack_h2(pb[0].x, pb[0].y); w0.y = pack_h2(pb[0].z, pb[0].w);
            w0.z = pack_h2(pb[1].x, pb[1].y); w0.w = pack_h2(pb[1].z, pb[1].w);
            w1.x = pack_h2(pb[2].x, pb[2].y); w1.y = pack_h2(pb[2].z, pb[2].w);
            w1.z = pack_h2(pb[3].x, pb[3].y); w1.w = pack_h2(pb[3].z, pb[3].w);
            *(uint4*)(bs)     = w0;
            *(uint4*)(bs + 4) = w1;
        }
        if (kt + 1 < ntiles) {
            const float* bg = Bg + (kt+1)*32;
            #pragma unroll
            for (int c = 0; c < 4; c++) pb[c] = *(const float4*)(bg + c*4);
        }
        cpa_wait0();
        __syncthreads();
        if (kt + 1 < ntiles) {
            const __half* ag = Ag + (kt+1)*32;
            const unsigned ad = (buf ? aDst0 : aDst1);
            cpa16(ad,      ag,     asz);
            cpa16(ad + 16, ag + 8, asz);
        }
        cpa_commit();

        const unsigned ab = aBuf[buf];
        const unsigned bb = bBuf[buf];
        #pragma unroll
        for (int ks = 0; ks < 2; ks++) {
            const int kw = ks * 8;
            unsigned a[2][4], b[8][2];
            #pragma unroll
            for (int mt = 0; mt < 2; mt++)
                ldsm4(a[mt][0], a[mt][1], a[mt][2], a[mt][3],
                      ab + (unsigned)(((a_r + mt*16)*RS + kw + a_w) * 4));
            #pragma unroll
            for (int p = 0; p < 4; p++)
                ldsm4(b[2*p][0], b[2*p][1], b[2*p+1][0], b[2*p+1][1],
                      bb + (unsigned)(((b_r + p*16)*RS + kw + b_w) * 4));
            #pragma unroll
            for (int mt = 0; mt < 2; mt++)
                #pragma unroll
                for (int nt = 0; nt < 8; nt++)
                    mma_f16(acc[mt][nt], a[mt], b[nt]);
        }
    }

    #pragma unroll
    for (int mt = 0; mt < 2; mt++) {
        #pragma unroll
        for (int half = 0; half < 2; half++) {
            int lm = m0 + wm*32 + mt*16 + g + half*8;
            if (lm < M) {
                if (SHARED) {
                    float* Cp = Out + (long)lm * H_ + n0 + wn*64 + 2*tg;
                    #pragma unroll
                    for (int nt = 0; nt < 8; nt++) {
                        float2 v;
                        v.x = acc[mt][nt][half*2 + 0];
                        v.y = acc[mt][nt][half*2 + 1];
                        *(float2*)(Cp + nt*8) = v;
                    }
                } else {
                    int slot = dst[e*T_ + lm];
                    float* Cp = Out + (long)(slot >> 2) * H_ + n0 + wn*64 + 2*tg;
                    #pragma unroll
                    for (int nt = 0; nt < 8; nt++) {
                        red_add_v2(Cp + nt*8,
                                   RSCALE_ * acc[mt][nt][half*2 + 0],
                                   RSCALE_ * acc[mt][nt][half*2 + 1]);
                    }
                }
            }
        }
    }
}

// ---------------- launcher ----------------
extern "C" void kernel_launch(void* const* d_in, const int* in_sizes, int n_in,
                              void* d_out, int out_size) {
    const float* x        = (const float*)d_in[0];
    const float* gate_w   = (const float*)d_in[1];
    const float* e_bias   = (const float*)d_in[2];
    const float* w_gu     = (const float*)d_in[3];
    const float* w_dn     = (const float*)d_in[4];
    const float* s_wgu    = (const float*)d_in[5];
    const float* s_wdn    = (const float*)d_in[6];
    float* out = (float*)d_out;

    __half *p_x16, *p_act; float* p_wslot;
    int *p_cnt, *p_tok, *p_dst;
    cudaGetSymbolAddress((void**)&p_x16,   d_x16);
    cudaGetSymbolAddress((void**)&p_act,   d_act);
    cudaGetSymbolAddress((void**)&p_wslot, d_wslot);
    cudaGetSymbolAddress((void**)&p_cnt,   d_cnt);
    cudaGetSymbolAddress((void**)&p_tok,   d_tok);
    cudaGetSymbolAddress((void**)&p_dst,   d_dst);

    // 1. reset counters + shared-expert gather lists
    init_kernel<<<(T_ + 255)/256, 256>>>();

    // 1b. x -> fp16
    cvt_x_kernel<<<(T_*H_/8 + 255)/256, 256>>>(x);

    // 2. router (fp32 exact)
    router_kernel<<<T_, 512>>>(x, gate_w, e_bias);

    // 3. all gate_up + silu (+w): routed experts AND shared (z = E_)
    gu_silu_gemm<<<dim3(I_/64, T_/128, E_+1), 256>>>(
        p_x16, w_gu, s_wgu, p_act, p_cnt, p_tok, p_dst, p_wslot);

    // 4. shared down: plain store initializes out
    down_gemm<true><<<dim3(H_/128, T_/128, 1), 256>>>(
        p_act, s_wdn, out, p_cnt, p_dst);

    // 5. routed down: red.v2 accumulate 2.5*y into out
    down_gemm<false><<<dim3(H_/128, T_/128, E_), 256>>>(
        p_act, w_dn, out, p_cnt, p_dst);
}